// round 1
// baseline (speedup 1.0000x reference)
#include <cuda_runtime.h>
#include <math.h>

#define NRR 512
#define NAA 512
#define MAXG 4096

// Precomputed per-gaussian parameters (scratch via __device__ globals — no allocs).
// g_p0 = (rc, cc, A, B), g_p1 = (C, w, ext_r, ext_c)
// where exp(-0.5*mahal) = exp2(A*dr^2 + B*dr*dc + C*dc^2)
__device__ float4 g_p0[MAXG];
__device__ float4 g_p1[MAXG];

__global__ void prep_kernel(const float* __restrict__ pos,
                            const float* __restrict__ cov,
                            const float* __restrict__ inten, int N)
{
    int n = blockIdx.x * blockDim.x + threadIdx.x;
    if (n >= N) return;

    const float cb  = 0.8660254037844387f;   // cos(30deg)
    const float sb  = 0.5f;                  // sin(30deg)
    const float RCc = 5773.502691896258f;    // ALT/cos(beta)
    const float RPY = -2886.7513459481287f;  // radar pos y
    const float RPZ = 5000.0f;

    float dx = pos[n*3+0];
    float dy = pos[n*3+1] - RPY;
    float dz = pos[n*3+2] - RPZ;

    float Xr = dx;
    float Yr = -cb*dy - sb*dz;
    float Zr =  sb*dy - cb*dz;

    float Rmin = sqrtf(Yr*Yr + Zr*Zr + 1e-12f);
    float rc = Rmin + 256.0f - RCc;
    float cc = Xr + 256.0f;
    float u1 = Yr / Rmin;
    float u2 = Zr / Rmin;

    const float* S = cov + n*9;
    float S00=S[0], S01=S[1], S02=S[2], S11=S[4], S12=S[5], S22=S[8];

    // cov_r = R * Sigma * R^T (only the entries we need)
    float c00 = S00;
    float c10 = -cb*S01 - sb*S02;
    float c20 =  sb*S01 - cb*S02;
    float c11 = cb*cb*S11 + 2.0f*cb*sb*S12 + sb*sb*S22;
    float c12 = cb*sb*(S22 - S11) + (cb*cb - sb*sb)*S12;
    float c22 = sb*sb*S11 - 2.0f*sb*cb*S12 + cb*cb*S22;

    // cov2 = J cov_r J^T + 1e-4 I
    float a  = u1*u1*c11 + 2.0f*u1*u2*c12 + u2*u2*c22 + 1e-4f;
    float b  = u1*c10 + u2*c20;
    float d2 = c00 + 1e-4f;

    float det = a*d2 - b*b;
    float inv = 1.0f / det;
    float ia  =  d2 * inv;
    float ib  = -b  * inv;
    float idv =  a  * inv;
    float w   = inten[n] * 0.15915494309189535f * inv;   // I/(2*pi*det)

    const float L2E = 1.4426950408889634f;
    float A = -0.5f * L2E * ia;
    float B = -L2E * ib;
    float C = -0.5f * L2E * idv;

    // mahal > T=210 => fp32 exp underflows to exactly 0 (matches reference).
    const float T = 210.0f;
    float er = sqrtf(T * a);
    float ec = sqrtf(T * d2);

    g_p0[n] = make_float4(rc, cc, A, B);
    g_p1[n] = make_float4(C, w, er, ec);
}

__global__ __launch_bounds__(256) void render_kernel(float* __restrict__ out, int N)
{
    __shared__ int sIdx[1024];
    __shared__ int warpTot[8];
    __shared__ int warpOff[8];
    __shared__ int sCount;

    int tx = threadIdx.x, ty = threadIdx.y;
    int tid  = ty * 16 + tx;
    int lane = tid & 31;
    int wid  = tid >> 5;

    int col = blockIdx.x * 16 + tx;
    int row = blockIdx.y * 16 + ty;
    float rowf = (float)row;
    float colf = (float)col;
    float r0 = (float)(blockIdx.y * 16);
    float c0 = (float)(blockIdx.x * 16);

    float acc = 0.0f;

    for (int base = 0; base < N; base += 1024) {
        // ---- Phase A: deterministic bbox-cull + compaction (ascending gid order) ----
        unsigned msk = 0;
        int cnt = 0;
        int gfirst = base + tid * 4;
        #pragma unroll
        for (int j = 0; j < 4; j++) {
            int gid = gfirst + j;
            bool ok = false;
            if (gid < N) {
                float4 p0 = g_p0[gid];
                float4 p1 = g_p1[gid];
                ok = (p0.x + p1.z >= r0) && (p0.x - p1.z <= r0 + 15.0f) &&
                     (p0.y + p1.w >= c0) && (p0.y - p1.w <= c0 + 15.0f);
            }
            if (ok) { msk |= (1u << j); cnt++; }
        }
        // warp inclusive scan of counts
        int inc = cnt;
        #pragma unroll
        for (int d = 1; d < 32; d <<= 1) {
            int v = __shfl_up_sync(0xffffffffu, inc, d);
            if (lane >= d) inc += v;
        }
        if (lane == 31) warpTot[wid] = inc;
        __syncthreads();
        if (tid == 0) {
            int s = 0;
            #pragma unroll
            for (int w2 = 0; w2 < 8; w2++) { warpOff[w2] = s; s += warpTot[w2]; }
            sCount = s;
        }
        __syncthreads();
        int off = warpOff[wid] + inc - cnt;   // exclusive prefix
        #pragma unroll
        for (int j = 0; j < 4; j++)
            if (msk & (1u << j)) sIdx[off++] = gfirst + j;
        __syncthreads();

        // ---- Phase B: splat survivors onto this thread's pixel ----
        int M = sCount;
        #pragma unroll 2
        for (int i = 0; i < M; i++) {
            int gid = sIdx[i];
            float4 p0 = g_p0[gid];   // uniform address -> LDG broadcast, L1/L2 hit
            float4 p1 = g_p1[gid];
            float dr = rowf - p0.x;
            float dc = colf - p0.y;
            float t  = fmaf(p0.z, dr, p0.w * dc);   // A*dr + B*dc
            float q  = dc * dc;
            float m  = fmaf(t, dr, p1.x * q);       // A*dr^2 + B*dr*dc + C*dc^2
            float e;
            asm("ex2.approx.ftz.f32 %0, %1;" : "=f"(e) : "f"(m));
            acc = fmaf(p1.y, e, acc);
        }
        __syncthreads();   // smem reuse barrier for next chunk
    }

    out[row * NAA + col] = acc;
}

extern "C" void kernel_launch(void* const* d_in, const int* in_sizes, int n_in,
                              void* d_out, int out_size)
{
    const float* pos   = (const float*)d_in[0];
    const float* cov   = (const float*)d_in[1];
    const float* inten = (const float*)d_in[2];
    float* out = (float*)d_out;

    int N = in_sizes[2];          // intensities element count == N_GAUSS
    if (N > MAXG) N = MAXG;

    prep_kernel<<<(N + 255) / 256, 256>>>(pos, cov, inten, N);

    dim3 blk(16, 16);
    dim3 grd(NAA / 16, NRR / 16);
    render_kernel<<<grd, blk>>>(out, N);
}

// round 2
// speedup vs baseline: 1.1505x; 1.1505x over previous
#include <cuda_runtime.h>
#include <math.h>

#define NRR 512
#define NAA 512
#define CH 1024          // gaussians staged in smem per chunk

// Fused single-kernel SAR gaussian splatter.
// Each block: 32x32 pixel tile, 256 threads, 4 pixels/thread (same column).
// Phase 0: block redundantly computes all gaussian params -> smem (kills prep launch).
// Phase A: deterministic bbox cull + warp-scan compaction (ascending order).
// Phase B: splat survivors; params via broadcast LDS; 3 FMA + 1 MUFU per pixel.
__global__ __launch_bounds__(256) void sar_kernel(
    const float* __restrict__ pos,
    const float* __restrict__ cov,
    const float* __restrict__ inten,
    float* __restrict__ out, int N)
{
    __shared__ float4 sP0[CH];   // (rc, cc, A, B)
    __shared__ float4 sP1[CH];   // (C, w, ext_r, ext_c)
    __shared__ int    sIdx[CH];
    __shared__ int    warpTot[8];
    __shared__ int    warpOff[8];
    __shared__ int    sCount;

    const int tid  = threadIdx.x;
    const int lane = tid & 31;
    const int wid  = tid >> 5;
    const int tx   = tid & 31;      // column within tile
    const int ty   = tid >> 5;      // row group (0..7), rows ty+8k

    const int   col  = blockIdx.x * 32 + tx;
    const int   rowb = blockIdx.y * 32;
    const float colf = (float)col;
    const float rf0  = (float)(rowb + ty);
    const float r0   = (float)rowb;
    const float c0   = (float)(blockIdx.x * 32);

    const float cb  = 0.8660254037844387f;   // cos(30deg)
    const float sb  = 0.5f;                  // sin(30deg)
    const float RCc = 5773.502691896258f;    // ALT/cos(beta)
    const float RPY = -2886.7513459481287f;  // radar pos y
    const float RPZ = 5000.0f;
    const float L2E = 1.4426950408889634f;

    float acc0 = 0.f, acc1 = 0.f, acc2 = 0.f, acc3 = 0.f;

    for (int base = 0; base < N; base += CH) {
        const int chunkN = min(CH, N - base);

        // ---- Phase 0: per-gaussian param prep into smem ----
        for (int g = tid; g < chunkN; g += 256) {
            const int n = base + g;
            float dx = pos[n*3+0];
            float dy = pos[n*3+1] - RPY;
            float dz = pos[n*3+2] - RPZ;

            float Xr = dx;
            float Yr = -cb*dy - sb*dz;
            float Zr =  sb*dy - cb*dz;

            float Rmin = sqrtf(Yr*Yr + Zr*Zr + 1e-12f);
            float rc = Rmin + 256.0f - RCc;
            float cc = Xr + 256.0f;
            float u1 = Yr / Rmin;
            float u2 = Zr / Rmin;

            const float* S = cov + n*9;
            float S00=S[0], S01=S[1], S02=S[2], S11=S[4], S12=S[5], S22=S[8];

            float c10 = -cb*S01 - sb*S02;
            float c20 =  sb*S01 - cb*S02;
            float c11 = cb*cb*S11 + 2.0f*cb*sb*S12 + sb*sb*S22;
            float c12 = cb*sb*(S22 - S11) + (cb*cb - sb*sb)*S12;
            float c22 = sb*sb*S11 - 2.0f*sb*cb*S12 + cb*cb*S22;

            float a  = u1*u1*c11 + 2.0f*u1*u2*c12 + u2*u2*c22 + 1e-4f;
            float b  = u1*c10 + u2*c20;
            float d2 = S00 + 1e-4f;

            float det = a*d2 - b*b;
            float inv = 1.0f / det;
            float A = -0.5f * L2E * d2 * inv;
            float B =         L2E * b  * inv;
            float C = -0.5f * L2E * a  * inv;
            float w = inten[n] * 0.15915494309189535f * inv;

            // mahal > 210 => fp32 exp == 0 exactly (matches reference truncation)
            const float T = 210.0f;
            float er = sqrtf(T * a);
            float ec = sqrtf(T * d2);

            sP0[g] = make_float4(rc, cc, A, B);
            sP1[g] = make_float4(C, w, er, ec);
        }
        __syncthreads();

        // ---- Phase A: bbox cull + deterministic compaction ----
        unsigned msk = 0; int cnt = 0;
        const int gfirst = tid * 4;
        #pragma unroll
        for (int j = 0; j < 4; j++) {
            int g = gfirst + j;
            bool ok = false;
            if (g < chunkN) {
                float4 p0 = sP0[g];
                float4 p1 = sP1[g];
                ok = (p0.x + p1.z >= r0) && (p0.x - p1.z <= r0 + 31.0f) &&
                     (p0.y + p1.w >= c0) && (p0.y - p1.w <= c0 + 31.0f);
            }
            if (ok) { msk |= (1u << j); cnt++; }
        }
        int inc = cnt;
        #pragma unroll
        for (int d = 1; d < 32; d <<= 1) {
            int v = __shfl_up_sync(0xffffffffu, inc, d);
            if (lane >= d) inc += v;
        }
        if (lane == 31) warpTot[wid] = inc;
        __syncthreads();
        if (tid == 0) {
            int s = 0;
            #pragma unroll
            for (int w2 = 0; w2 < 8; w2++) { warpOff[w2] = s; s += warpTot[w2]; }
            sCount = s;
        }
        __syncthreads();
        int off = warpOff[wid] + inc - cnt;
        #pragma unroll
        for (int j = 0; j < 4; j++)
            if (msk & (1u << j)) sIdx[off++] = gfirst + j;
        __syncthreads();

        // ---- Phase B: splat survivors, 4 rows per thread ----
        const int M = sCount;
        #pragma unroll 2
        for (int i = 0; i < M; i++) {
            const int g = sIdx[i];            // uniform -> broadcast LDS
            const float4 p0 = sP0[g];
            const float4 p1 = sP1[g];

            float dc  = colf - p0.y;
            float Bdc = p0.w * dc;
            float Cq  = p1.x * dc * dc;
            float drb = rf0 - p0.x;
            float A   = p0.z;
            float w   = p1.y;

            float dr0 = drb;
            float dr1 = drb + 8.0f;
            float dr2 = drb + 16.0f;
            float dr3 = drb + 24.0f;

            float t0 = fmaf(A, dr0, Bdc);
            float t1 = fmaf(A, dr1, Bdc);
            float t2 = fmaf(A, dr2, Bdc);
            float t3 = fmaf(A, dr3, Bdc);

            float m0 = fmaf(t0, dr0, Cq);
            float m1 = fmaf(t1, dr1, Cq);
            float m2 = fmaf(t2, dr2, Cq);
            float m3 = fmaf(t3, dr3, Cq);

            float e0, e1, e2, e3;
            asm("ex2.approx.ftz.f32 %0, %1;" : "=f"(e0) : "f"(m0));
            asm("ex2.approx.ftz.f32 %0, %1;" : "=f"(e1) : "f"(m1));
            asm("ex2.approx.ftz.f32 %0, %1;" : "=f"(e2) : "f"(m2));
            asm("ex2.approx.ftz.f32 %0, %1;" : "=f"(e3) : "f"(m3));

            acc0 = fmaf(w, e0, acc0);
            acc1 = fmaf(w, e1, acc1);
            acc2 = fmaf(w, e2, acc2);
            acc3 = fmaf(w, e3, acc3);
        }
        __syncthreads();   // smem reuse for next chunk
    }

    out[(rowb + ty      ) * NAA + col] = acc0;
    out[(rowb + ty +  8 ) * NAA + col] = acc1;
    out[(rowb + ty + 16 ) * NAA + col] = acc2;
    out[(rowb + ty + 24 ) * NAA + col] = acc3;
}

extern "C" void kernel_launch(void* const* d_in, const int* in_sizes, int n_in,
                              void* d_out, int out_size)
{
    const float* pos   = (const float*)d_in[0];
    const float* cov   = (const float*)d_in[1];
    const float* inten = (const float*)d_in[2];
    float* out = (float*)d_out;

    int N = in_sizes[2];   // intensities element count == N_GAUSS

    dim3 grd(NAA / 32, NRR / 32);
    sar_kernel<<<grd, 256>>>(pos, cov, inten, out, N);
}